// round 9
// baseline (speedup 1.0000x reference)
#include <cuda_runtime.h>
#include <cuda_bf16.h>
#include <math.h>
#include <stdint.h>

// ---------------- constants ----------------
constexpr int T = 2048, D = 2048, H = 16, DN = 128, DR = 64, DV = 128;
constexpr int QL = 768, KL = 512, FF = 8192, E = 32, EF = 1024;
constexpr int QD = DN + DR;          // 192
constexpr int KVD = KL + DR;         // 576
constexpr int NQKV = QL + KVD;       // 1344
constexpr int KVBD = H * (DN + DV);  // 4096
constexpr int QTOT = H * QD;         // 3072
constexpr int HDV = H * DV;          // 2048

constexpr int BM = 128, BN = 128, BK = 32;
constexpr int PAD = 40;
constexpr int TILE_ELEMS = 128 * PAD;
constexpr int GSMEM = 2 * 4 * TILE_ELEMS * 2;  // 81920 B (bf16 kernel)
constexpr int GPERS = 304;

// int8 GEMM geometry: CTA 128x64, BK=64 bytes
constexpr int BKI = 64;
constexpr int PADI = 80;                  // bytes per smem row
constexpr int IA_TILE = 128 * PADI;       // 10240
constexpr int IB_TILE = 64 * PADI;        // 5120
constexpr int ISTAGE = 2 * IA_TILE + 2 * IB_TILE;  // 30720
constexpr int IGSMEM = 2 * ISTAGE;        // 61440

typedef __nv_bfloat16 bf16;

// ---------------- PTX helpers ----------------
__device__ __forceinline__ uint32_t smem_to_u32(const void* p) {
    uint32_t a;
    asm("{ .reg .u64 t; cvta.to.shared.u64 t, %1; cvt.u32.u64 %0, t; }" : "=r"(a) : "l"(p));
    return a;
}
__device__ __forceinline__ void cp16(uint32_t smem_dst, const void* gsrc, bool valid) {
    int sz = valid ? 16 : 0;
    asm volatile("cp.async.cg.shared.global [%0], [%1], 16, %2;\n"
                 :: "r"(smem_dst), "l"(gsrc), "r"(sz));
}
#define CP_COMMIT() asm volatile("cp.async.commit_group;\n" ::: "memory")
#define CP_WAIT0()  asm volatile("cp.async.wait_group 0;\n" ::: "memory")

__device__ __forceinline__ void ldsm_x4(uint32_t* r, uint32_t addr) {
    asm volatile("ldmatrix.sync.aligned.m8n8.x4.shared.b16 {%0,%1,%2,%3}, [%4];\n"
                 : "=r"(r[0]), "=r"(r[1]), "=r"(r[2]), "=r"(r[3]) : "r"(addr));
}
__device__ __forceinline__ void mma16816(float* c, const uint32_t* a, uint32_t b0, uint32_t b1) {
    asm volatile(
        "mma.sync.aligned.m16n8k16.row.col.f32.bf16.bf16.f32 "
        "{%0,%1,%2,%3}, {%4,%5,%6,%7}, {%8,%9}, {%0,%1,%2,%3};\n"
        : "+f"(c[0]), "+f"(c[1]), "+f"(c[2]), "+f"(c[3])
        : "r"(a[0]), "r"(a[1]), "r"(a[2]), "r"(a[3]), "r"(b0), "r"(b1));
}
__device__ __forceinline__ void mma_s8(int* c, const uint32_t* a, uint32_t b0, uint32_t b1) {
    asm volatile(
        "mma.sync.aligned.m16n8k32.row.col.s32.s8.s8.s32 "
        "{%0,%1,%2,%3}, {%4,%5,%6,%7}, {%8,%9}, {%0,%1,%2,%3};\n"
        : "+r"(c[0]), "+r"(c[1]), "+r"(c[2]), "+r"(c[3])
        : "r"(a[0]), "r"(a[1]), "r"(a[2]), "r"(a[3]), "r"(b0), "r"(b1));
}

// ---------------- scratch (device globals) ----------------
__device__ float g_res[(size_t)T * D];
__device__ float g_h[(size_t)T * D];
__device__ float g_moe[(size_t)T * D];
__device__ float g_qkv[(size_t)T * NQKV];
__device__ float g_q[(size_t)T * QTOT];
__device__ float g_kvb[(size_t)T * KVBD];
__device__ float g_attno[(size_t)T * HDV];
__device__ float g_scores[(size_t)H * T * T];
__device__ float g_gu[(size_t)T * 2 * FF];
__device__ float g_mgu[(size_t)2 * T * 2 * EF];
__device__ float g_my[(size_t)2 * T * D];
__device__ float g_logits[(size_t)T * E];
// bf16 hi/lo activations (attention + MoE paths)
__device__ bf16 x_h[(size_t)T * D], x_l[(size_t)T * D];
__device__ bf16 qq_h[(size_t)T * QTOT], qq_l[(size_t)T * QTOT];
__device__ bf16 kh_h[(size_t)T * QTOT], kh_l[(size_t)T * QTOT];
__device__ bf16 vt_h[(size_t)H * DV * T], vt_l[(size_t)H * DV * T];
__device__ bf16 P_h[(size_t)H * T * T], P_l[(size_t)H * T * T];
__device__ bf16 mx_h[(size_t)2 * T * D], mx_l[(size_t)2 * T * D];
__device__ bf16 mh_h[(size_t)2 * T * EF], mh_l[(size_t)2 * T * EF];
// int8 two-digit activations + row scales
__device__ int8_t xq1[(size_t)T * D], xq2[(size_t)T * D];
__device__ float sc_x[T];
__device__ int8_t qlnq1[(size_t)T * QL], qlnq2[(size_t)T * QL];
__device__ float sc_qln[T];
__device__ int8_t kvcnq1[(size_t)T * KL], kvcnq2[(size_t)T * KL];
__device__ float sc_kvcn[T];
__device__ int8_t ffq1[(size_t)T * FF], ffq2[(size_t)T * FF];
__device__ float sc_ff[T];
__device__ int8_t aoq1[(size_t)T * HDV], aoq2[(size_t)T * HDV];
__device__ float sc_ao[T];
// int8 two-digit weights [N][K] + per-N-row scales
__device__ int8_t wqkvq1[(size_t)2 * NQKV * D], wqkvq2[(size_t)2 * NQKV * D];
__device__ float sc_wqkv[2 * NQKV];
__device__ int8_t wqbq1[(size_t)2 * QTOT * QL], wqbq2[(size_t)2 * QTOT * QL];
__device__ float sc_wqb[2 * QTOT];
__device__ int8_t wkvbq1[(size_t)2 * KVBD * KL], wkvbq2[(size_t)2 * KVBD * KL];
__device__ float sc_wkvb[2 * KVBD];
__device__ int8_t woq1[(size_t)2 * D * HDV], woq2[(size_t)2 * D * HDV];
__device__ float sc_wo[2 * D];
__device__ int8_t wguq1[(size_t)2 * 2 * FF * D], wguq2[(size_t)2 * 2 * FF * D];
__device__ float sc_wgu[2 * 2 * FF];
__device__ int8_t wdq1[(size_t)2 * D * FF], wdq2[(size_t)2 * D * FF];
__device__ float sc_wd[2 * D];
__device__ int8_t rwq1[(size_t)E * D], rwq2[(size_t)E * D];
__device__ float sc_rw[E];
// MoE bf16 weights
__device__ bf16 mwguT_h[(size_t)E * 2 * EF * D], mwguT_l[(size_t)E * 2 * EF * D];
__device__ bf16 mwdT_h[(size_t)E * D * EF], mwdT_l[(size_t)E * D * EF];
// routing
__device__ int g_expid[2 * T];
__device__ int g_slot[2 * T];
__device__ int g_rowOf[2 * T];
__device__ float g_gate[2 * T];
__device__ int g_cnt[E];
__device__ int g_off[E];

// ---------------- small helpers ----------------
__device__ __forceinline__ void wr_hl(bf16* h, bf16* l, size_t i, float x) {
    bf16 hi = __float2bfloat16(x);
    h[i] = hi;
    l[i] = __float2bfloat16(x - __bfloat162float(hi));
}
__device__ __forceinline__ float blockReduceSum(float v) {
    __shared__ float sh[32];
    int lane = threadIdx.x & 31, wid = threadIdx.x >> 5;
    #pragma unroll
    for (int o = 16; o; o >>= 1) v += __shfl_down_sync(0xffffffffu, v, o);
    if (lane == 0) sh[wid] = v;
    __syncthreads();
    int nw = (blockDim.x + 31) >> 5;
    v = (threadIdx.x < nw) ? sh[threadIdx.x] : 0.f;
    if (wid == 0) {
        #pragma unroll
        for (int o = 16; o; o >>= 1) v += __shfl_down_sync(0xffffffffu, v, o);
        if (lane == 0) sh[0] = v;
    }
    __syncthreads();
    float r = sh[0];
    __syncthreads();
    return r;
}
__device__ __forceinline__ float blockReduceMax(float v) {
    __shared__ float sh[32];
    int lane = threadIdx.x & 31, wid = threadIdx.x >> 5;
    #pragma unroll
    for (int o = 16; o; o >>= 1) v = fmaxf(v, __shfl_down_sync(0xffffffffu, v, o));
    if (lane == 0) sh[wid] = v;
    __syncthreads();
    int nw = (blockDim.x + 31) >> 5;
    v = (threadIdx.x < nw) ? sh[threadIdx.x] : -1e30f;
    if (wid == 0) {
        #pragma unroll
        for (int o = 16; o; o >>= 1) v = fmaxf(v, __shfl_down_sync(0xffffffffu, v, o));
        if (lane == 0) sh[0] = v;
    }
    __syncthreads();
    float r = sh[0];
    __syncthreads();
    return r;
}
__device__ __forceinline__ void quant2(float x, float inv_s, int8_t& q1, int8_t& q2) {
    float v = x * inv_s;
    float r1 = rintf(v);
    q1 = (int8_t)r1;
    q2 = (int8_t)rintf((v - r1) * 128.f);
}

// =======================================================================
// int8 two-digit balanced split GEMM. C[m,n] += sa[m]*sb[n]*(acc1 + acc12/128)
// A: [M][K] int8 x2, B: [N][K] int8 x2 (K-major). CTA 128x64, BK=64.
// =======================================================================
__global__ void __launch_bounds__(256, 2)
igemm_split_k(const int8_t* __restrict__ A1, const int8_t* __restrict__ A2,
              const float* __restrict__ sa,
              const int8_t* __restrict__ B1, const int8_t* __restrict__ B2,
              const float* __restrict__ sb,
              float* __restrict__ C, int M, int N, int K,
              int lda, int ldb, int ldc, int mt, int nt) {
    int nch = K / BKI;
    long U = (long)mt * nt * nch;
    int G = gridDim.x;
    long u0 = (long)blockIdx.x * U / G;
    long u1 = ((long)blockIdx.x + 1) * U / G;

    extern __shared__ int8_t ism[];
    uint32_t smb = smem_to_u32(ism);
    int tid = threadIdx.x, lane = tid & 31, wid = tid >> 5;
    int warp_m = wid >> 2, warp_n = wid & 3;  // 2x4 warps; warp tile 64m x 16n
    uint32_t frag = (uint32_t)(lane & 15) * PADI + ((uint32_t)(lane >> 4) << 4);
    int rrow = lane >> 2, rcol = (lane & 3) * 2;

    while (u0 < u1) {
        int tile = (int)(u0 / nch);
        int c0 = (int)(u0 % nch);
        long rem = u1 - (long)tile * nch;
        int c1 = rem < (long)nch ? (int)rem : nch;

        int bm = (tile % mt) * 128;
        int bn = (tile / mt) * 64;
        int rcA = (M - bm) < 128 ? (M - bm) : 128;
        int rcB = (N - bn) < 64 ? (N - bn) : 64;

        int acc1[4][2][4], acc12[4][2][4];
        #pragma unroll
        for (int i = 0; i < 4; i++)
            #pragma unroll
            for (int j = 0; j < 2; j++)
                #pragma unroll
                for (int q = 0; q < 4; q++) { acc1[i][j][q] = 0; acc12[i][j][q] = 0; }

        auto load_chunk = [&](int c, int buf) {
            int k0 = c * BKI;
            uint32_t base = smb + (uint32_t)buf * ISTAGE;
            int row = tid >> 2, ch = (tid & 3) * 16;
            #pragma unroll
            for (int it = 0; it < 2; it++) {
                int r = row + it * 64;
                bool v = r < rcA;
                long ga = (long)(bm + (v ? r : 0)) * lda + k0 + ch;
                uint32_t so = (uint32_t)r * PADI + ch;
                cp16(base + so, A1 + ga, v);
                cp16(base + IA_TILE + so, A2 + ga, v);
            }
            {
                bool v = row < rcB;
                long gb = (long)(bn + (v ? row : 0)) * ldb + k0 + ch;
                uint32_t so = (uint32_t)row * PADI + ch;
                cp16(base + 2 * IA_TILE + so, B1 + gb, v);
                cp16(base + 2 * IA_TILE + IB_TILE + so, B2 + gb, v);
            }
        };

        load_chunk(c0, 0);
        CP_COMMIT();

        for (int c = c0; c < c1; c++) {
            CP_WAIT0();
            __syncthreads();
            if (c + 1 < c1) { load_chunk(c + 1, (c - c0 + 1) & 1); CP_COMMIT(); }

            uint32_t base = smb + (uint32_t)((c - c0) & 1) * ISTAGE;
            #pragma unroll
            for (int ks = 0; ks < 2; ks++) {
                uint32_t ob = (uint32_t)(warp_n * 16) * PADI + (uint32_t)(ks * 32) + frag;
                uint32_t b1r[4], b2r[4];
                ldsm_x4(b1r, base + 2 * IA_TILE + ob);
                ldsm_x4(b2r, base + 2 * IA_TILE + IB_TILE + ob);
                #pragma unroll
                for (int mf = 0; mf < 4; mf++) {
                    uint32_t oa = (uint32_t)(warp_m * 64 + mf * 16) * PADI + (uint32_t)(ks * 32) + frag;
                    uint32_t a1r[4], a2r[4];
                    ldsm_x4(a1r, base + oa);
                    ldsm_x4(a2r, base + IA_TILE + oa);
                    #pragma unroll
                    for (int nf = 0; nf < 2; nf++) {
                        mma_s8(acc1[mf][nf], a1r, b1r[nf], b1r[nf + 2]);
                        mma_s8(acc12[mf][nf], a1r, b2r[nf], b2r[nf + 2]);
                        mma_s8(acc12[mf][nf], a2r, b1r[nf], b1r[nf + 2]);
                    }
                }
            }
            __syncthreads();
        }

        const float inv128 = 0.0078125f;
        #pragma unroll
        for (int mf = 0; mf < 4; mf++) {
            #pragma unroll
            for (int nf = 0; nf < 2; nf++) {
                int m0 = bm + warp_m * 64 + mf * 16 + rrow;
                int n0 = bn + warp_n * 16 + nf * 8 + rcol;
                #pragma unroll
                for (int half = 0; half < 2; half++) {
                    int mm = m0 + half * 8;
                    if (mm >= M) continue;
                    #pragma unroll
                    for (int jj = 0; jj < 2; jj++) {
                        int nn = n0 + jj;
                        if (nn >= N) continue;
                        float v = sa[mm] * sb[nn] *
                                  ((float)acc1[mf][nf][half * 2 + jj] +
                                   (float)acc12[mf][nf][half * 2 + jj] * inv128);
                        atomicAdd(&C[(long)mm * ldc + nn], v);
                    }
                }
            }
        }
        __syncthreads();
        u0 = (long)tile * nch + c1;
    }
}

// =======================================================================
// bf16x3 GEMM via mma.sync (R5 core) — scores / AV / MoE seg only
// =======================================================================
template <bool SEG>
__global__ void __launch_bounds__(256, 2)
bgemm_k(const bf16* __restrict__ Ah, const bf16* __restrict__ Al,
        const bf16* __restrict__ Bh, const bf16* __restrict__ Bl,
        float* __restrict__ C, int M, int N, int K,
        int lda, int ldb, int ldc, long sA, long sB, long sC,
        int cskip, int kcap, const int* __restrict__ off, const int* __restrict__ cnt) {
    int z = blockIdx.z;
    if (SEG) {
        int rs = off[z];
        M = cnt[z];
        Ah += (long)rs * lda; Al += (long)rs * lda;
        C += (long)rs * ldc;
        Bh += (long)z * sB; Bl += (long)z * sB;
    } else {
        Ah += (long)z * sA; Al += (long)z * sA;
        Bh += (long)z * sB; Bl += (long)z * sB;
        C += (long)z * sC;
    }
    int bid = blockIdx.y * gridDim.x + blockIdx.x;
    int mt = gridDim.y;
    int bm = (bid % mt) * BM;
    int bn = (bid / mt) * BN;
    if (bm >= M) return;
    if (cskip && bn > bm + 127) return;
    int Klim = kcap ? (K < bm + 128 ? K : bm + 128) : K;
    int nch = Klim / BK;

    extern __shared__ bf16 sm[];
    uint32_t smb = smem_to_u32(sm);
    int tid = threadIdx.x, lane = tid & 31, wid = tid >> 5;
    int warp_m = wid >> 2, warp_n = wid & 3;

    float acc[4][4][4];
    #pragma unroll
    for (int i = 0; i < 4; i++)
        #pragma unroll
        for (int j = 0; j < 4; j++)
            #pragma unroll
            for (int q = 0; q < 4; q++) acc[i][j][q] = 0.f;

    int rcA = (M - bm) < BM ? (M - bm) : BM;
    int rcB = (N - bn) < BN ? (N - bn) : BN;

    int srow0 = tid >> 2, sch = tid & 3;
    auto load_chunk = [&](int c, int buf) {
        int k0 = c * BK;
        #pragma unroll
        for (int it = 0; it < 2; it++) {
            int row = srow0 + it * 64;
            uint32_t soff = (uint32_t)(row * PAD + sch * 8) * 2;
            bool vA = row < rcA;
            bool vB = row < rcB;
            long ga = (long)(bm + (vA ? row : 0)) * lda + k0 + sch * 8;
            long gb = (long)(bn + (vB ? row : 0)) * ldb + k0 + sch * 8;
            uint32_t base = smb + (uint32_t)buf * 4 * TILE_ELEMS * 2;
            cp16(base + 0 * TILE_ELEMS * 2 + soff, Ah + ga, vA);
            cp16(base + 1 * TILE_ELEMS * 2 + soff, Al + ga, vA);
            cp16(base + 2 * TILE_ELEMS * 2 + soff, Bh + gb, vB);
            cp16(base + 3 * TILE_ELEMS * 2 + soff, Bl + gb, vB);
        }
    };

    uint32_t aoff = ((uint32_t)((lane & 15) * PAD) + ((lane >> 4) << 3)) * 2;
    uint32_t boff = ((uint32_t)(((lane & 7) + ((lane >> 1) & 8)) * PAD) + (lane & 8)) * 2;

    load_chunk(0, 0);
    CP_COMMIT();

    for (int c = 0; c < nch; c++) {
        CP_WAIT0();
        __syncthreads();
        if (c + 1 < nch) { load_chunk(c + 1, (c + 1) & 1); CP_COMMIT(); }

        uint32_t base = smb + (uint32_t)(c & 1) * 4 * TILE_ELEMS * 2;
        uint32_t tAh = base, tAl = base + TILE_ELEMS * 2;
        uint32_t tBh = base + 2 * TILE_ELEMS * 2, tBl = base + 3 * TILE_ELEMS * 2;

        #pragma unroll
        for (int ks = 0; ks < 2; ks++) {
            uint32_t bh[2][4], bl[2][4];
            #pragma unroll
            for (int nf2 = 0; nf2 < 2; nf2++) {
                uint32_t o = (uint32_t)((warp_n * 32 + nf2 * 16) * PAD) * 2 + (uint32_t)(ks * 32) + boff;
                ldsm_x4(bh[nf2], tBh + o);
                ldsm_x4(bl[nf2], tBl + o);
            }
            #pragma unroll
            for (int mf = 0; mf < 4; mf++) {
                uint32_t ah[4], al[4];
                uint32_t o = (uint32_t)((warp_m * 64 + mf * 16) * PAD) * 2 + (uint32_t)(ks * 32) + aoff;
                ldsm_x4(ah, tAh + o);
                ldsm_x4(al, tAl + o);
                #pragma unroll
                for (int nf = 0; nf < 4; nf++) {
                    int n2 = nf >> 1, pb = (nf & 1) * 2;
                    float* cc = acc[mf][nf];
                    mma16816(cc, ah, bh[n2][pb], bh[n2][pb + 1]);
                    mma16816(cc, ah, bl[n2][pb], bl[n2][pb + 1]);
                    mma16816(cc, al, bh[n2][pb], bh[n2][pb + 1]);
                }
            }
        }
        __syncthreads();
    }

    int rrow = lane >> 2, rcol = (lane & 3) * 2;
    #pragma unroll
    for (int mf = 0; mf < 4; mf++) {
        #pragma unroll
        for (int nf = 0; nf < 4; nf++) {
            int m0 = bm + warp_m * 64 + mf * 16 + rrow;
            int n0 = bn + warp_n * 32 + nf * 8 + rcol;
            float* cc = acc[mf][nf];
            #pragma unroll
            for (int half = 0; half < 2; half++) {
                int mm = m0 + half * 8;
                if (mm >= M) continue;
                #pragma unroll
                for (int jj = 0; jj < 2; jj++) {
                    int nn = n0 + jj;
                    if (nn < N) C[(long)mm * ldc + nn] = cc[half * 2 + jj];
                }
            }
        }
    }
}

// ---------------- weight quantize + transpose: W[K][N] -> q1/q2[N][K], s[N] ----------------
__global__ void wquantT_k(const float* __restrict__ W, int8_t* __restrict__ O1,
                          int8_t* __restrict__ O2, float* __restrict__ Os,
                          int K, int N, long zso, long zss) {
    long z = blockIdx.z;
    W += z * (long)K * N;
    O1 += z * zso;
    O2 += z * zso;
    Os += z * zss;
    int n0 = blockIdx.x * 32;
    int tx = threadIdx.x, ty = threadIdx.y;  // (32,8)

    __shared__ float red[8][33];
    __shared__ float sinv[32];
    float mx = 0.f;
    for (int k = ty; k < K; k += 8) mx = fmaxf(mx, fabsf(W[(long)k * N + n0 + tx]));
    red[ty][tx] = mx;
    __syncthreads();
    if (ty == 0) {
        float m = red[0][tx];
        #pragma unroll
        for (int i = 1; i < 8; i++) m = fmaxf(m, red[i][tx]);
        float s = fmaxf(m, 1e-20f) / 127.f;
        Os[n0 + tx] = s;
        sinv[tx] = 1.f / s;
    }
    __syncthreads();

    __shared__ float tile[32][33];
    for (int k0 = 0; k0 < K; k0 += 32) {
        #pragma unroll
        for (int i = 0; i < 4; i++)
            tile[ty + i * 8][tx] = W[(long)(k0 + ty + i * 8) * N + n0 + tx];
        __syncthreads();
        #pragma unroll
        for (int i = 0; i < 4; i++) {
            int nl = ty + i * 8;
            int n = n0 + nl, k = k0 + tx;
            float v = tile[tx][nl] * sinv[nl];
            float r1 = rintf(v);
            O1[(long)n * K + k] = (int8_t)r1;
            O2[(long)n * K + k] = (int8_t)rintf((v - r1) * 128.f);
        }
        __syncthreads();
    }
}

// ---------------- MoE weight transpose (bf16 hi/lo) ----------------
__global__ void wtrans_k(const float* __restrict__ W, bf16* __restrict__ Oh,
                         bf16* __restrict__ Ol, int K, int N, long zso) {
    long z = blockIdx.z;
    W += z * (long)K * N;
    Oh += z * zso;
    Ol += z * zso;
    __shared__ float tile[32][33];
    int n0 = blockIdx.x * 32, k0 = blockIdx.y * 32;
    int tx = threadIdx.x, ty = threadIdx.y;
    #pragma unroll
    for (int i = 0; i < 4; i++)
        tile[ty + i * 8][tx] = W[(long)(k0 + ty + i * 8) * N + n0 + tx];
    __syncthreads();
    #pragma unroll
    for (int i = 0; i < 4; i++) {
        int n = n0 + ty + i * 8, k = k0 + tx;
        wr_hl(Oh, Ol, (size_t)n * K + k, tile[tx][ty + i * 8]);
    }
}

// ---------------- row kernels: norm / quantize ----------------
// RMS norm -> int8 pair + scale; optional bf16 hi/lo out (for x). cols <= 2048.
__global__ void rms_q_k(const float* __restrict__ x, const float* __restrict__ w,
                        int8_t* __restrict__ q1, int8_t* __restrict__ q2,
                        float* __restrict__ qs, bf16* __restrict__ oh,
                        bf16* __restrict__ ol, int cols, int ldx, int ldo) {
    __shared__ float buf[2048];
    long row = blockIdx.x;
    const float* xr = x + row * ldx;
    float s = 0.f;
    for (int i = threadIdx.x; i < cols; i += blockDim.x) { float v = xr[i]; s += v * v; }
    s = blockReduceSum(s);
    float sc = rsqrtf(s / cols + 1e-6f);
    float mx = 0.f;
    for (int i = threadIdx.x; i < cols; i += blockDim.x) {
        float y = xr[i] * sc * w[i];
        buf[i] = y;
        mx = fmaxf(mx, fabsf(y));
    }
    __syncthreads();
    mx = blockReduceMax(mx);
    float qsc = fmaxf(mx, 1e-20f) / 127.f;
    float inv = 1.f / qsc;
    if (threadIdx.x == 0) qs[row] = qsc;
    for (int i = threadIdx.x; i < cols; i += blockDim.x) {
        quant2(buf[i], inv, q1[row * ldo + i], q2[row * ldo + i]);
        if (oh) wr_hl(oh, ol, row * ldo + i, buf[i]);
    }
}

// add + RMS norm -> res, bf16 hi/lo (x), int8 pair + scale
__global__ void addnorm_q_k(const float* __restrict__ a, const float* __restrict__ b,
                            const float* __restrict__ w, float* __restrict__ res,
                            bf16* __restrict__ oh, bf16* __restrict__ ol,
                            int8_t* __restrict__ q1, int8_t* __restrict__ q2,
                            float* __restrict__ qs) {
    __shared__ float buf[2048];
    long row = blockIdx.x;
    const float* ar = a + row * D;
    const float* br = b + row * D;
    float* rr = res + row * D;
    float s = 0.f;
    for (int i = threadIdx.x; i < D; i += blockDim.x) {
        float v = ar[i] + br[i];
        rr[i] = v;
        s += v * v;
    }
    s = blockReduceSum(s);
    float sc = rsqrtf(s / D + 1e-6f);
    float mx = 0.f;
    for (int i = threadIdx.x; i < D; i += blockDim.x) {
        float y = rr[i] * sc * w[i];
        buf[i] = y;
        mx = fmaxf(mx, fabsf(y));
    }
    __syncthreads();
    mx = blockReduceMax(mx);
    float qsc = fmaxf(mx, 1e-20f) / 127.f;
    float inv = 1.f / qsc;
    if (threadIdx.x == 0) qs[row] = qsc;
    for (int i = threadIdx.x; i < D; i += blockDim.x) {
        quant2(buf[i], inv, q1[row * D + i], q2[row * D + i]);
        wr_hl(oh, ol, row * D + i, buf[i]);
    }
}

// silu(g)*u over g_gu rows -> ff int8 pair + scale (recompute 2-pass, row=FF)
__global__ void silu_q_k() {
    long row = blockIdx.x;
    const float* gr = g_gu + row * (2 * FF);
    float mx = 0.f;
    for (int c = threadIdx.x; c < FF; c += blockDim.x) {
        float g = gr[c], u = gr[FF + c];
        float y = g / (1.f + expf(-g)) * u;
        mx = fmaxf(mx, fabsf(y));
    }
    mx = blockReduceMax(mx);
    float qsc = fmaxf(mx, 1e-20f) / 127.f;
    float inv = 1.f / qsc;
    if (threadIdx.x == 0) sc_ff[row] = qsc;
    for (int c = threadIdx.x; c < FF; c += blockDim.x) {
        float g = gr[c], u = gr[FF + c];
        float y = g / (1.f + expf(-g)) * u;
        quant2(y, inv, ffq1[row * FF + c], ffq2[row * FF + c]);
    }
}

// quantize fp32 rows (ao): cols <= 2048
__global__ void quantrows_k(const float* __restrict__ X, int8_t* __restrict__ q1,
                            int8_t* __restrict__ q2, float* __restrict__ qs, int cols) {
    __shared__ float buf[2048];
    long row = blockIdx.x;
    const float* xr = X + row * cols;
    float mx = 0.f;
    for (int i = threadIdx.x; i < cols; i += blockDim.x) {
        float v = xr[i];
        buf[i] = v;
        mx = fmaxf(mx, fabsf(v));
    }
    __syncthreads();
    mx = blockReduceMax(mx);
    float qsc = fmaxf(mx, 1e-20f) / 127.f;
    float inv = 1.f / qsc;
    if (threadIdx.x == 0) qs[row] = qsc;
    for (int i = threadIdx.x; i < cols; i += blockDim.x)
        quant2(buf[i], inv, q1[row * cols + i], q2[row * cols + i]);
}

// ---------------- attention elementwise (bf16 path, unchanged) ----------------
__global__ void rope_cvt_q_k(const float* __restrict__ q, const int* __restrict__ pos) {
    int t = blockIdx.x;
    float fp = (float)pos[t];
    for (int e = threadIdx.x; e < QTOT; e += blockDim.x) {
        int h = e / QD, d = e % QD;
        const float* qr = q + (size_t)t * QTOT + h * QD;
        float v;
        if (d < DN) {
            v = qr[d];
        } else {
            int j = d - DN;
            int i = j & 31;
            float inv = 1.f / powf(10000.f, (float)i * (2.f / 64.f));
            float sn, cs;
            sincosf(fp * inv, &sn, &cs);
            float x1 = qr[DN + i], x2 = qr[DN + i + 32];
            v = (j < 32) ? (x1 * cs - x2 * sn) : (x2 * cs + x1 * sn);
        }
        wr_hl(qq_h, qq_l, (size_t)t * QTOT + e, v);
    }
}

__global__ void build_kh_k(const int* __restrict__ pos) {
    int t = blockIdx.x;
    __shared__ float kr[64];
    int tid = threadIdx.x;
    if (tid < 32) {
        int i = tid;
        float inv = 1.f / powf(10000.f, (float)i * (2.f / 64.f));
        float sn, cs;
        sincosf((float)pos[t] * inv, &sn, &cs);
        const float* kb = g_qkv + (size_t)t * NQKV + QL + KL;
        float x1 = kb[i], x2 = kb[i + 32];
        kr[i] = x1 * cs - x2 * sn;
        kr[i + 32] = x2 * cs + x1 * sn;
    }
    __syncthreads();
    for (int e = tid; e < QTOT; e += blockDim.x) {
        int h = e / QD, d = e % QD;
        float v = (d < DN) ? g_kvb[(size_t)t * KVBD + h * (DN + DV) + d] : kr[d - DN];
        wr_hl(kh_h, kh_l, (size_t)t * QTOT + e, v);
    }
}

__global__ void build_vt_k() {
    int t = blockIdx.x;
    const float* row = g_kvb + (size_t)t * KVBD;
    for (int e = threadIdx.x; e < H * DV; e += blockDim.x) {
        int h = e >> 7, d = e & 127;
        wr_hl(vt_h, vt_l, (size_t)e * T + t, row[h * (DN + DV) + DN + d]);
    }
}

__global__ void softmaxP_k() {
    int t = blockIdx.x, h = blockIdx.y;
    const float* row = g_scores + ((size_t)h * T + t) * (size_t)T;
    size_t po = ((size_t)h * T + t) * (size_t)T;
    int n = t + 1;
    const float alpha = 0.07216878364870322f;
    float m = -1e30f;
    for (int i = threadIdx.x; i < n; i += blockDim.x) m = fmaxf(m, row[i] * alpha);
    m = blockReduceMax(m);
    float s = 0.f;
    for (int i = threadIdx.x; i < n; i += blockDim.x) s += expf(row[i] * alpha - m);
    s = blockReduceSum(s);
    float inv = 1.f / s;
    for (int i = threadIdx.x; i < n; i += blockDim.x)
        wr_hl(P_h, P_l, po + i, expf(row[i] * alpha - m) * inv);
    bf16 zz = __float2bfloat16(0.f);
    for (int i = n + threadIdx.x; i < T; i += blockDim.x) { P_h[po + i] = zz; P_l[po + i] = zz; }
}

// ---------------- MoE (bf16 path) ----------------
__global__ void silumul2_k() {
    long idx = (long)blockIdx.x * blockDim.x + threadIdx.x;
    if (idx >= (long)2 * T * EF) return;
    long r = idx / EF;
    int c = (int)(idx % EF);
    float g = g_mgu[r * (2 * EF) + c], u = g_mgu[r * (2 * EF) + EF + c];
    wr_hl(mh_h, mh_l, idx, g / (1.f + expf(-g)) * u);
}
__global__ void top2_k() {
    int t = blockIdx.x * blockDim.x + threadIdx.x;
    if (t >= T) return;
    const float* l = g_logits + (size_t)t * E;
    int i0 = 0;
    float v0 = l[0];
    for (int i = 1; i < E; i++)
        if (l[i] > v0) { v0 = l[i]; i0 = i; }
    int i1 = -1;
    float v1 = -1e30f;
    for (int i = 0; i < E; i++)
        if (i != i0 && l[i] > v1) { v1 = l[i]; i1 = i; }
    float e = expf(v1 - v0);
    g_expid[2 * t] = i0;
    g_expid[2 * t + 1] = i1;
    g_gate[2 * t] = 1.f / (1.f + e);
    g_gate[2 * t + 1] = e / (1.f + e);
}
__global__ void zero_cnt_k() { if (threadIdx.x < E) g_cnt[threadIdx.x] = 0; }
__global__ void count_k() {
    int p = blockIdx.x * blockDim.x + threadIdx.x;
    if (p < 2 * T) g_slot[p] = atomicAdd(&g_cnt[g_expid[p]], 1);
}
__global__ void scan_k() {
    if (threadIdx.x == 0) {
        int o = 0;
        for (int e = 0; e < E; e++) { g_off[e] = o; o += g_cnt[e]; }
    }
}
__global__ void gather_k() {
    int p = blockIdx.x;
    int row = g_off[g_expid[p]] + g_slot[p];
    if (threadIdx.x == 0) g_rowOf[p] = row;
    size_t src = (size_t)(p >> 1) * D, dst = (size_t)row * D;
    for (int i = threadIdx.x; i < D; i += blockDim.x) {
        mx_h[dst + i] = x_h[src + i];
        mx_l[dst + i] = x_l[src + i];
    }
}
__global__ void moecomb_k() {
    long idx = (long)blockIdx.x * blockDim.x + threadIdx.x;
    if (idx >= (long)T * D) return;
    long t = idx / D;
    int d = (int)(idx % D);
    g_moe[idx] = g_gate[2 * t] * g_my[(size_t)g_rowOf[2 * t] * D + d] +
                 g_gate[2 * t + 1] * g_my[(size_t)g_rowOf[2 * t + 1] * D + d];
}
__global__ void add_k(const float* __restrict__ a, const float* __restrict__ b,
                      float* __restrict__ o, long n) {
    long idx = (long)blockIdx.x * blockDim.x + threadIdx.x;
    if (idx < n) o[idx] = a[idx] + b[idx];
}

// ---------------- host helpers ----------------
static void igemm(const int8_t* A1, const int8_t* A2, const float* sa,
                  const int8_t* B1, const int8_t* B2, const float* sb,
                  float* C, int M, int N, int K, int lda, int ldb, int ldc) {
    cudaMemsetAsync(C, 0, (size_t)M * ldc * sizeof(float));
    int mt = (M + 127) / 128, nt = (N + 63) / 64;
    long U = (long)mt * nt * (K / BKI);
    int G = U < GPERS ? (int)U : GPERS;
    igemm_split_k<<<G, 256, IGSMEM>>>(A1, A2, sa, B1, B2, sb, C, M, N, K, lda, ldb, ldc, mt, nt);
}
static void bgemm_f(const bf16* Ah, const bf16* Al, const bf16* Bh, const bf16* Bl,
                    float* C, int M, int N, int K, int lda, int ldb, int ldc,
                    long sA, long sB, long sC, int batch, int cskip, int kcap) {
    dim3 g((N + BN - 1) / BN, (M + BM - 1) / BM, batch);
    bgemm_k<false><<<g, 256, GSMEM>>>(Ah, Al, Bh, Bl, C, M, N, K, lda, ldb, ldc,
                                      sA, sB, sC, cskip, kcap, nullptr, nullptr);
}
static void bgemm_seg(const bf16* Ah, const bf16* Al, const bf16* Bh, const bf16* Bl,
                      float* C, int N, int K, int lda, int ldb, int ldc, long sB,
                      const int* off, const int* cnt) {
    dim3 g((N + BN - 1) / BN, (2 * T + BM - 1) / BM, E);
    bgemm_k<true><<<g, 256, GSMEM>>>(Ah, Al, Bh, Bl, C, 0, N, K, lda, ldb, ldc,
                                     0, sB, 0, 0, 0, off, cnt);
}

extern "C" void kernel_launch(void* const* d_in, const int* in_sizes, int n_in,
                              void* d_out, int out_size) {
    const float* hidden = (const float*)d_in[0];
    const int* pos = (const int*)d_in[1];
    const float* ln_in = (const float*)d_in[2];
    const float* ln_post = (const float*)d_in[3];
    const float* wqa = (const float*)d_in[4];
    const float* qnorm = (const float*)d_in[5];
    const float* wqb = (const float*)d_in[6];
    const float* wkva = (const float*)d_in[7];
    const float* kvnorm = (const float*)d_in[8];
    const float* wkvb = (const float*)d_in[9];
    const float* wo = (const float*)d_in[10];
    const float* wgu = (const float*)d_in[11];
    const float* wd = (const float*)d_in[12];
    const float* rw = (const float*)d_in[13];
    const float* mwg = (const float*)d_in[14];
    const float* mwu = (const float*)d_in[15];
    const float* mwd = (const float*)d_in[16];
    float* out = (float*)d_out;

    cudaFuncSetAttribute(bgemm_k<false>, cudaFuncAttributeMaxDynamicSharedMemorySize, GSMEM);
    cudaFuncSetAttribute(bgemm_k<true>, cudaFuncAttributeMaxDynamicSharedMemorySize, GSMEM);
    cudaFuncSetAttribute(igemm_split_k, cudaFuncAttributeMaxDynamicSharedMemorySize, IGSMEM);

    void* p;
#define SYMF(name) cudaGetSymbolAddress(&p, name); float* p_##name = (float*)p;
#define SYMB(name) cudaGetSymbolAddress(&p, name); bf16* p_##name = (bf16*)p;
#define SYMI(name) cudaGetSymbolAddress(&p, name); int* p_##name = (int*)p;
#define SYMQ(name) cudaGetSymbolAddress(&p, name); int8_t* p_##name = (int8_t*)p;
    SYMF(g_res) SYMF(g_h) SYMF(g_moe) SYMF(g_qkv) SYMF(g_q) SYMF(g_kvb) SYMF(g_attno)
    SYMF(g_scores) SYMF(g_gu) SYMF(g_mgu) SYMF(g_my) SYMF(g_logits)
    SYMF(sc_x) SYMF(sc_qln) SYMF(sc_kvcn) SYMF(sc_ff) SYMF(sc_ao)
    SYMF(sc_wqkv) SYMF(sc_wqb) SYMF(sc_wkvb) SYMF(sc_wo) SYMF(sc_wgu) SYMF(sc_wd) SYMF(sc_rw)
    SYMB(x_h) SYMB(x_l) SYMB(qq_h) SYMB(qq_l) SYMB(kh_h) SYMB(kh_l)
    SYMB(vt_h) SYMB(vt_l) SYMB(P_h) SYMB(P_l) SYMB(mx_h) SYMB(mx_l) SYMB(mh_h) SYMB(mh_l)
    SYMB(mwguT_h) SYMB(mwguT_l) SYMB(mwdT_h) SYMB(mwdT_l)
    SYMQ(xq1) SYMQ(xq2) SYMQ(qlnq1) SYMQ(qlnq2) SYMQ(kvcnq1) SYMQ(kvcnq2)
    SYMQ(ffq1) SYMQ(ffq2) SYMQ(aoq1) SYMQ(aoq2)
    SYMQ(wqkvq1) SYMQ(wqkvq2) SYMQ(wqbq1) SYMQ(wqbq2) SYMQ(wkvbq1) SYMQ(wkvbq2)
    SYMQ(woq1) SYMQ(woq2) SYMQ(wguq1) SYMQ(wguq2) SYMQ(wdq1) SYMQ(wdq2)
    SYMQ(rwq1) SYMQ(rwq2)
    SYMI(g_cnt) SYMI(g_off)
#undef SYMF
#undef SYMB
#undef SYMI
#undef SYMQ

    dim3 tb(32, 8);
    long zqkv = (long)NQKV * D;

    // 0: x norm + quant (dual bf16 out unused until addnorm, pass anyway)
    rms_q_k<<<T, 256>>>(hidden, ln_in, p_xq1, p_xq2, p_sc_x, p_x_h, p_x_l, D, D, D);
    // 1,2: qkv weight quant (combined buffer)
    wquantT_k<<<dim3(QL / 32, 1, 2), tb>>>(wqa, p_wqkvq1, p_wqkvq2, p_sc_wqkv,
                                           D, QL, zqkv, NQKV);
    wquantT_k<<<dim3(KVD / 32, 1, 2), tb>>>(wkva, p_wqkvq1 + (size_t)QL * D,
                                            p_wqkvq2 + (size_t)QL * D, p_sc_wqkv + QL,
                                            D, KVD, zqkv, NQKV);
    // 3: qkv int8 GEMM (ncu target)
    igemm(p_xq1, p_xq2, p_sc_x, p_wqkvq1, p_wqkvq2, p_sc_wqkv,
          p_g_qkv, T, NQKV, D, D, D, NQKV);
    // remaining weight preps
    wquantT_k<<<dim3(QTOT / 32, 1, 2), tb>>>(wqb, p_wqbq1, p_wqbq2, p_sc_wqb,
                                             QL, QTOT, (long)QTOT * QL, QTOT);
    wquantT_k<<<dim3(KVBD / 32, 1, 2), tb>>>(wkvb, p_wkvbq1, p_wkvbq2, p_sc_wkvb,
                                             KL, KVBD, (long)KVBD * KL, KVBD);
    wquantT_k<<<dim3(D / 32, 1, 2), tb>>>(wo, p_woq1, p_woq2, p_sc_wo,
                                          HDV, D, (long)D * HDV, D);
    wquantT_k<<<dim3(2 * FF / 32, 1, 2), tb>>>(wgu, p_wguq1, p_wguq2, p_sc_wgu,
                                               D, 2 * FF, (long)2 * FF * D, 2 * FF);
    wquantT_k<<<dim3(D / 32, 1, 2), tb>>>(wd, p_wdq1, p_wdq2, p_sc_wd,
                                          FF, D, (long)D * FF, D);
    wquantT_k<<<dim3(E / 32, 1, 1), tb>>>(rw, p_rwq1, p_rwq2, p_sc_rw, D, E, 0, 0);
    wtrans_k<<<dim3(EF / 32, D / 32, E), tb>>>(mwg, p_mwguT_h, p_mwguT_l, D, EF,
                                               (long)2 * EF * D);
    wtrans_k<<<dim3(EF / 32, D / 32, E), tb>>>(mwu, p_mwguT_h + (size_t)EF * D,
                                               p_mwguT_l + (size_t)EF * D, D, EF,
                                               (long)2 * EF * D);
    wtrans_k<<<dim3(D / 32, EF / 32, E), tb>>>(mwd, p_mwdT_h, p_mwdT_l, EF, D, (long)D * EF);

    auto mla = [&](int l, float* outbuf, bool qkv_done) {
        if (!qkv_done)
            igemm(p_xq1, p_xq2, p_sc_x, p_wqkvq1 + (size_t)l * zqkv,
                  p_wqkvq2 + (size_t)l * zqkv, p_sc_wqkv + (size_t)l * NQKV,
                  p_g_qkv, T, NQKV, D, D, D, NQKV);
        rms_q_k<<<T, 256>>>(p_g_qkv, qnorm + (size_t)l * QL, p_qlnq1, p_qlnq2, p_sc_qln,
                            nullptr, nullptr, QL, NQKV, QL);
        igemm(p_qlnq1, p_qlnq2, p_sc_qln, p_wqbq1 + (size_t)l * QTOT * QL,
              p_wqbq2 + (size_t)l * QTOT * QL, p_sc_wqb + (size_t)l * QTOT,
              p_g_q, T, QTOT, QL, QL, QL, QTOT);
        rms_q_k<<<T, 256>>>(p_g_qkv + QL, kvnorm + (size_t)l * KL, p_kvcnq1, p_kvcnq2,
                            p_sc_kvcn, nullptr, nullptr, KL, NQKV, KL);
        igemm(p_kvcnq1, p_kvcnq2, p_sc_kvcn, p_wkvbq1 + (size_t)l * KVBD * KL,
              p_wkvbq2 + (size_t)l * KVBD * KL, p_sc_wkvb + (size_t)l * KVBD,
              p_g_kvb, T, KVBD, KL, KL, KL, KVBD);
        rope_cvt_q_k<<<T, 256>>>(p_g_q, pos);
        build_kh_k<<<T, 256>>>(pos);
        build_vt_k<<<T, 256>>>();
        bgemm_f(p_qq_h, p_qq_l, p_kh_h, p_kh_l, p_g_scores, T, T, QD,
                QTOT, QTOT, T, QD, QD, (long)T * T, H, 1, 0);
        softmaxP_k<<<dim3(T, H), 256>>>();
        bgemm_f(p_P_h, p_P_l, p_vt_h, p_vt_l, p_g_attno, T, DV, T,
                T, T, HDV, (long)T * T, (long)DV * T, DV, H, 0, 1);
        quantrows_k<<<T, 256>>>(p_g_attno, p_aoq1, p_aoq2, p_sc_ao, HDV);
        igemm(p_aoq1, p_aoq2, p_sc_ao, p_woq1 + (size_t)l * D * HDV,
              p_woq2 + (size_t)l * D * HDV, p_sc_wo + (size_t)l * D,
              outbuf, T, D, HDV, HDV, HDV, D);
    };

    auto mlp = [&](int l, float* outbuf) {
        igemm(p_xq1, p_xq2, p_sc_x, p_wguq1 + (size_t)l * 2 * FF * D,
              p_wguq2 + (size_t)l * 2 * FF * D, p_sc_wgu + (size_t)l * 2 * FF,
              p_g_gu, T, 2 * FF, D, D, D, 2 * FF);
        silu_q_k<<<T, 256>>>();
        igemm(p_ffq1, p_ffq2, p_sc_ff, p_wdq1 + (size_t)l * D * FF,
              p_wdq2 + (size_t)l * D * FF, p_sc_wd + (size_t)l * D,
              outbuf, T, D, FF, FF, FF, D);
    };

    // ================= forward =================
    mla(0, p_g_h, true);
    addnorm_q_k<<<T, 256>>>(p_g_h, hidden, ln_post, p_g_res, p_x_h, p_x_l,
                            p_xq1, p_xq2, p_sc_x);

    // ---- MoE ----
    igemm(p_xq1, p_xq2, p_sc_x, p_rwq1, p_rwq2, p_sc_rw, p_g_logits, T, E, D, D, D, E);
    top2_k<<<(T + 255) / 256, 256>>>();
    zero_cnt_k<<<1, 32>>>();
    count_k<<<(2 * T + 255) / 256, 256>>>();
    scan_k<<<1, 32>>>();
    gather_k<<<2 * T, 256>>>();
    bgemm_seg(p_mx_h, p_mx_l, p_mwguT_h, p_mwguT_l, p_g_mgu, 2 * EF, D, D, D, 2 * EF,
              (long)2 * EF * D, p_g_off, p_g_cnt);
    silumul2_k<<<(int)(((long)2 * T * EF + 255) / 256), 256>>>();
    bgemm_seg(p_mh_h, p_mh_l, p_mwdT_h, p_mwdT_l, p_g_my, D, EF, EF, EF, D,
              (long)D * EF, p_g_off, p_g_cnt);
    moecomb_k<<<(int)(((long)T * D + 255) / 256), 256>>>();

    // ---- MLP layer 0 ----
    mlp(0, p_g_h);
    addnorm_q_k<<<T, 256>>>(p_g_h, p_g_res, ln_in + D, p_g_res, p_x_h, p_x_l,
                            p_xq1, p_xq2, p_sc_x);

    // ---- layer 1 ----
    mla(1, p_g_h, false);
    addnorm_q_k<<<T, 256>>>(p_g_h, p_g_res, ln_post + D, p_g_res, p_x_h, p_x_l,
                            p_xq1, p_xq2, p_sc_x);
    mlp(1, p_g_h);

    add_k<<<(int)(((long)T * D + 255) / 256), 256>>>(p_g_h, p_g_moe, out, (long)T * D);
}

// round 12
// speedup vs baseline: 2.1177x; 2.1177x over previous
#include <cuda_runtime.h>
#include <cuda_bf16.h>
#include <math.h>
#include <stdint.h>

// ---------------- constants ----------------
constexpr int T = 2048, D = 2048, H = 16, DN = 128, DR = 64, DV = 128;
constexpr int QL = 768, KL = 512, FF = 8192, E = 32, EF = 1024;
constexpr int QD = DN + DR;          // 192
constexpr int KVD = KL + DR;         // 576
constexpr int NQKV = QL + KVD;       // 1344
constexpr int KVBD = H * (DN + DV);  // 4096
constexpr int QTOT = H * QD;         // 3072
constexpr int HDV = H * DV;          // 2048

constexpr int BM = 128, BN = 128, BK = 32;
constexpr int PAD = 40;                       // smem leading dim (elements; 80B rows, 16B-aligned)
constexpr int TILE_ELEMS = 128 * PAD;         // 5120 elems = 10240 B
constexpr int GSMEM = 2 * 4 * TILE_ELEMS * 2; // 81920 B
constexpr int GPERS = 304;                    // 2 CTAs x 152 SMs

typedef __nv_bfloat16 bf16;

// ---------------- PTX helpers ----------------
__device__ __forceinline__ uint32_t smem_to_u32(const void* p) {
    uint32_t a;
    asm("{ .reg .u64 t; cvta.to.shared.u64 t, %1; cvt.u32.u64 %0, t; }" : "=r"(a) : "l"(p));
    return a;
}
__device__ __forceinline__ void cp16(uint32_t smem_dst, const void* gsrc, bool valid) {
    int sz = valid ? 16 : 0;
    asm volatile("cp.async.cg.shared.global [%0], [%1], 16, %2;\n"
                 :: "r"(smem_dst), "l"(gsrc), "r"(sz));
}
#define CP_COMMIT() asm volatile("cp.async.commit_group;\n" ::: "memory")
#define CP_WAIT0()  asm volatile("cp.async.wait_group 0;\n" ::: "memory")

__device__ __forceinline__ void ldsm_x4(uint32_t* r, uint32_t addr) {
    asm volatile("ldmatrix.sync.aligned.m8n8.x4.shared.b16 {%0,%1,%2,%3}, [%4];\n"
                 : "=r"(r[0]), "=r"(r[1]), "=r"(r[2]), "=r"(r[3]) : "r"(addr));
}
__device__ __forceinline__ void mma_bf(float* c, const uint32_t* a, uint32_t b0, uint32_t b1) {
    asm volatile(
        "mma.sync.aligned.m16n8k16.row.col.f32.bf16.bf16.f32 "
        "{%0,%1,%2,%3}, {%4,%5,%6,%7}, {%8,%9}, {%0,%1,%2,%3};\n"
        : "+f"(c[0]), "+f"(c[1]), "+f"(c[2]), "+f"(c[3])
        : "r"(a[0]), "r"(a[1]), "r"(a[2]), "r"(a[3]), "r"(b0), "r"(b1));
}

// ---------------- scratch (device globals) ----------------
__device__ float g_res[(size_t)T * D];
__device__ float g_h[(size_t)T * D];
__device__ float g_moe[(size_t)T * D];
__device__ float g_qkv[(size_t)T * NQKV];
__device__ float g_q[(size_t)T * QTOT];
__device__ float g_kvb[(size_t)T * KVBD];
__device__ float g_attno[(size_t)T * HDV];
__device__ float g_scores[(size_t)H * T * T];
__device__ float g_gu[(size_t)T * 2 * FF];
__device__ float g_mgu[(size_t)2 * T * 2 * EF];
__device__ float g_my[(size_t)2 * T * D];
__device__ float g_logits[(size_t)T * E];
// bf16 hi/lo activations
__device__ bf16 x_h[(size_t)T * D], x_l[(size_t)T * D];
__device__ bf16 qln_h[(size_t)T * QL], qln_l[(size_t)T * QL];
__device__ bf16 qq_h[(size_t)T * QTOT], qq_l[(size_t)T * QTOT];
__device__ bf16 kvcn_h[(size_t)T * KL], kvcn_l[(size_t)T * KL];
__device__ bf16 kh_h[(size_t)T * QTOT], kh_l[(size_t)T * QTOT];
__device__ bf16 vt_h[(size_t)H * DV * T], vt_l[(size_t)H * DV * T];
__device__ bf16 P_h[(size_t)H * T * T], P_l[(size_t)H * T * T];
__device__ bf16 ao_h[(size_t)T * HDV], ao_l[(size_t)T * HDV];
__device__ bf16 ff_h[(size_t)T * FF], ff_l[(size_t)T * FF];
__device__ bf16 mx_h[(size_t)2 * T * D], mx_l[(size_t)2 * T * D];
__device__ bf16 mh_h[(size_t)2 * T * EF], mh_l[(size_t)2 * T * EF];
// bf16 hi/lo weights transposed to [N][K]
__device__ bf16 wqkvT_h[(size_t)2 * NQKV * D], wqkvT_l[(size_t)2 * NQKV * D];
__device__ bf16 wqbT_h[(size_t)2 * QTOT * QL], wqbT_l[(size_t)2 * QTOT * QL];
__device__ bf16 wkvbT_h[(size_t)2 * KVBD * KL], wkvbT_l[(size_t)2 * KVBD * KL];
__device__ bf16 woT_h[(size_t)2 * D * D], woT_l[(size_t)2 * D * D];
__device__ bf16 wguT_h[(size_t)2 * 2 * FF * D], wguT_l[(size_t)2 * 2 * FF * D];
__device__ bf16 wdT_h[(size_t)2 * D * FF], wdT_l[(size_t)2 * D * FF];
__device__ bf16 rwT_h[(size_t)E * D], rwT_l[(size_t)E * D];
__device__ bf16 mwguT_h[(size_t)E * 2 * EF * D], mwguT_l[(size_t)E * 2 * EF * D];
__device__ bf16 mwdT_h[(size_t)E * D * EF], mwdT_l[(size_t)E * D * EF];
// routing
__device__ int g_expid[2 * T];
__device__ int g_slot[2 * T];
__device__ int g_rowOf[2 * T];
__device__ float g_gate[2 * T];
__device__ int g_cnt[E];
__device__ int g_off[E];

// ---------------- small helpers ----------------
__device__ __forceinline__ void wr_hl(bf16* h, bf16* l, size_t i, float x) {
    bf16 hi = __float2bfloat16(x);
    h[i] = hi;
    l[i] = __float2bfloat16(x - __bfloat162float(hi));
}
__device__ __forceinline__ float blockReduceSum(float v) {
    __shared__ float sh[32];
    int lane = threadIdx.x & 31, wid = threadIdx.x >> 5;
    #pragma unroll
    for (int o = 16; o; o >>= 1) v += __shfl_down_sync(0xffffffffu, v, o);
    if (lane == 0) sh[wid] = v;
    __syncthreads();
    int nw = (blockDim.x + 31) >> 5;
    v = (threadIdx.x < nw) ? sh[threadIdx.x] : 0.f;
    if (wid == 0) {
        #pragma unroll
        for (int o = 16; o; o >>= 1) v += __shfl_down_sync(0xffffffffu, v, o);
        if (lane == 0) sh[0] = v;
    }
    __syncthreads();
    float r = sh[0];
    __syncthreads();
    return r;
}
__device__ __forceinline__ float blockReduceMax(float v) {
    __shared__ float sh[32];
    int lane = threadIdx.x & 31, wid = threadIdx.x >> 5;
    #pragma unroll
    for (int o = 16; o; o >>= 1) v = fmaxf(v, __shfl_down_sync(0xffffffffu, v, o));
    if (lane == 0) sh[wid] = v;
    __syncthreads();
    int nw = (blockDim.x + 31) >> 5;
    v = (threadIdx.x < nw) ? sh[threadIdx.x] : -1e30f;
    if (wid == 0) {
        #pragma unroll
        for (int o = 16; o; o >>= 1) v = fmaxf(v, __shfl_down_sync(0xffffffffu, v, o));
        if (lane == 0) sh[0] = v;
    }
    __syncthreads();
    float r = sh[0];
    __syncthreads();
    return r;
}

// =======================================================================
// bf16x3 GEMM (R8 core: 2-stage, 2 CTA/SM) — scores (cskip) / MoE seg
// =======================================================================
template <bool SEG>
__global__ void __launch_bounds__(256, 2)
bgemm_k(const bf16* __restrict__ Ah, const bf16* __restrict__ Al,
        const bf16* __restrict__ Bh, const bf16* __restrict__ Bl,
        float* __restrict__ C, int M, int N, int K,
        int lda, int ldb, int ldc, long sA, long sB, long sC,
        int cskip, const int* __restrict__ off, const int* __restrict__ cnt) {
    int z = blockIdx.z;
    if (SEG) {
        int rs = off[z];
        M = cnt[z];
        Ah += (long)rs * lda; Al += (long)rs * lda;
        C += (long)rs * ldc;
        Bh += (long)z * sB; Bl += (long)z * sB;
    } else {
        Ah += (long)z * sA; Al += (long)z * sA;
        Bh += (long)z * sB; Bl += (long)z * sB;
        C += (long)z * sC;
    }
    int bid = blockIdx.y * gridDim.x + blockIdx.x;
    int mt = gridDim.y;
    int bm = (bid % mt) * BM;
    int bn = (bid / mt) * BN;
    if (bm >= M) return;
    if (cskip && bn > bm + 127) return;
    int nch = K / BK;

    extern __shared__ bf16 sm[];
    uint32_t smb = smem_to_u32(sm);
    int tid = threadIdx.x, lane = tid & 31, wid = tid >> 5;
    int warp_m = wid >> 2, warp_n = wid & 3;

    float acc[4][4][4];
    #pragma unroll
    for (int i = 0; i < 4; i++)
        #pragma unroll
        for (int j = 0; j < 4; j++)
            #pragma unroll
            for (int q = 0; q < 4; q++) acc[i][j][q] = 0.f;

    int rcA = (M - bm) < BM ? (M - bm) : BM;
    int rcB = (N - bn) < BN ? (N - bn) : BN;

    int srow0 = tid >> 2, sch = tid & 3;
    auto load_chunk = [&](int c, int buf) {
        int k0 = c * BK;
        uint32_t base = smb + (uint32_t)buf * 4 * TILE_ELEMS * 2;
        #pragma unroll
        for (int it = 0; it < 2; it++) {
            int row = srow0 + it * 64;
            uint32_t soff = (uint32_t)(row * PAD + sch * 8) * 2;
            bool vA = row < rcA;
            bool vB = row < rcB;
            long ga = (long)(bm + (vA ? row : 0)) * lda + k0 + sch * 8;
            long gb = (long)(bn + (vB ? row : 0)) * ldb + k0 + sch * 8;
            cp16(base + 0 * TILE_ELEMS * 2 + soff, Ah + ga, vA);
            cp16(base + 1 * TILE_ELEMS * 2 + soff, Al + ga, vA);
            cp16(base + 2 * TILE_ELEMS * 2 + soff, Bh + gb, vB);
            cp16(base + 3 * TILE_ELEMS * 2 + soff, Bl + gb, vB);
        }
    };

    uint32_t aoff = ((uint32_t)((lane & 15) * PAD) + ((lane >> 4) << 3)) * 2;
    uint32_t boff = ((uint32_t)(((lane & 7) + ((lane >> 1) & 8)) * PAD) + (lane & 8)) * 2;

    load_chunk(0, 0);
    CP_COMMIT();

    for (int c = 0; c < nch; c++) {
        CP_WAIT0();
        __syncthreads();
        if (c + 1 < nch) { load_chunk(c + 1, (c + 1) & 1); CP_COMMIT(); }

        uint32_t base = smb + (uint32_t)(c & 1) * 4 * TILE_ELEMS * 2;
        uint32_t tAh = base, tAl = base + TILE_ELEMS * 2;
        uint32_t tBh = base + 2 * TILE_ELEMS * 2, tBl = base + 3 * TILE_ELEMS * 2;

        #pragma unroll
        for (int ks = 0; ks < 2; ks++) {
            uint32_t bh[2][4], bl[2][4];
            #pragma unroll
            for (int nf2 = 0; nf2 < 2; nf2++) {
                uint32_t o = (uint32_t)((warp_n * 32 + nf2 * 16) * PAD) * 2 + (uint32_t)(ks * 32) + boff;
                ldsm_x4(bh[nf2], tBh + o);
                ldsm_x4(bl[nf2], tBl + o);
            }
            #pragma unroll
            for (int mf = 0; mf < 4; mf++) {
                uint32_t ah[4], al[4];
                uint32_t o = (uint32_t)((warp_m * 64 + mf * 16) * PAD) * 2 + (uint32_t)(ks * 32) + aoff;
                ldsm_x4(ah, tAh + o);
                ldsm_x4(al, tAl + o);
                #pragma unroll
                for (int nf = 0; nf < 4; nf++) {
                    int n2 = nf >> 1, pb = (nf & 1) * 2;
                    float* cc = acc[mf][nf];
                    mma_bf(cc, ah, bh[n2][pb], bh[n2][pb + 1]);
                    mma_bf(cc, ah, bl[n2][pb], bl[n2][pb + 1]);
                    mma_bf(cc, al, bh[n2][pb], bh[n2][pb + 1]);
                }
            }
        }
        __syncthreads();
    }

    int rrow = lane >> 2, rcol = (lane & 3) * 2;
    #pragma unroll
    for (int mf = 0; mf < 4; mf++) {
        #pragma unroll
        for (int nf = 0; nf < 4; nf++) {
            int m0 = bm + warp_m * 64 + mf * 16 + rrow;
            int n0 = bn + warp_n * 32 + nf * 8 + rcol;
            float* cc = acc[mf][nf];
            #pragma unroll
            for (int half = 0; half < 2; half++) {
                int mm = m0 + half * 8;
                if (mm >= M) continue;
                #pragma unroll
                for (int jj = 0; jj < 2; jj++) {
                    int nn = n0 + jj;
                    if (nn < N) C[(long)mm * ldc + nn] = cc[half * 2 + jj];
                }
            }
        }
    }
}

// =======================================================================
// Balanced-range split GEMM (R8 core; store-if-full epilogue)
// =======================================================================
__global__ void __launch_bounds__(256, 2)
sgemm_split_k(const bf16* __restrict__ Ah, const bf16* __restrict__ Al,
              const bf16* __restrict__ Bh, const bf16* __restrict__ Bl,
              float* __restrict__ C, int M, int N, int K,
              int lda, int ldb, int ldc, int mt, int nt) {
    int nch = K / BK;
    long U = (long)mt * nt * nch;
    int G = gridDim.x;
    long u0 = (long)blockIdx.x * U / G;
    long u1 = ((long)blockIdx.x + 1) * U / G;

    extern __shared__ bf16 sm[];
    uint32_t smb = smem_to_u32(sm);
    int tid = threadIdx.x, lane = tid & 31, wid = tid >> 5;
    int warp_m = wid >> 2, warp_n = wid & 3;
    int srow0 = tid >> 2, sch = tid & 3;
    uint32_t aoff = ((uint32_t)((lane & 15) * PAD) + ((lane >> 4) << 3)) * 2;
    uint32_t boff = ((uint32_t)(((lane & 7) + ((lane >> 1) & 8)) * PAD) + (lane & 8)) * 2;
    int rrow = lane >> 2, rcol = (lane & 3) * 2;

    while (u0 < u1) {
        int tile = (int)(u0 / nch);
        int c0 = (int)(u0 % nch);
        long rem = u1 - (long)tile * nch;
        int c1 = rem < (long)nch ? (int)rem : nch;

        int bm = (tile % mt) * BM;
        int bn = (tile / mt) * BN;
        int rcA = (M - bm) < BM ? (M - bm) : BM;
        int rcB = (N - bn) < BN ? (N - bn) : BN;
        bool full = (c0 == 0) && (c1 == nch);

        float acc[4][4][4];
        #pragma unroll
        for (int i = 0; i < 4; i++)
            #pragma unroll
            for (int j = 0; j < 4; j++)
                #pragma unroll
                for (int q = 0; q < 4; q++) acc[i][j][q] = 0.f;

        auto load_chunk = [&](int c, int buf) {
            int k0 = c * BK;
            uint32_t base = smb + (uint32_t)buf * 4 * TILE_ELEMS * 2;
            #pragma unroll
            for (int it = 0; it < 2; it++) {
                int row = srow0 + it * 64;
                uint32_t soff = (uint32_t)(row * PAD + sch * 8) * 2;
                bool vA = row < rcA;
                bool vB = row < rcB;
                long ga = (long)(bm + (vA ? row : 0)) * lda + k0 + sch * 8;
                long gb = (long)(bn + (vB ? row : 0)) * ldb + k0 + sch * 8;
                cp16(base + 0 * TILE_ELEMS * 2 + soff, Ah + ga, vA);
                cp16(base + 1 * TILE_ELEMS * 2 + soff, Al + ga, vA);
                cp16(base + 2 * TILE_ELEMS * 2 + soff, Bh + gb, vB);
                cp16(base + 3 * TILE_ELEMS * 2 + soff, Bl + gb, vB);
            }
        };

        load_chunk(c0, 0);
        CP_COMMIT();

        for (int c = c0; c < c1; c++) {
            CP_WAIT0();
            __syncthreads();
            if (c + 1 < c1) { load_chunk(c + 1, (c - c0 + 1) & 1); CP_COMMIT(); }

            uint32_t base = smb + (uint32_t)((c - c0) & 1) * 4 * TILE_ELEMS * 2;
            uint32_t tAh = base, tAl = base + TILE_ELEMS * 2;
            uint32_t tBh = base + 2 * TILE_ELEMS * 2, tBl = base + 3 * TILE_ELEMS * 2;

            #pragma unroll
            for (int ks = 0; ks < 2; ks++) {
                uint32_t bh[2][4], bl[2][4];
                #pragma unroll
                for (int nf2 = 0; nf2 < 2; nf2++) {
                    uint32_t o = (uint32_t)((warp_n * 32 + nf2 * 16) * PAD) * 2 + (uint32_t)(ks * 32) + boff;
                    ldsm_x4(bh[nf2], tBh + o);
                    ldsm_x4(bl[nf2], tBl + o);
                }
                #pragma unroll
                for (int mf = 0; mf < 4; mf++) {
                    uint32_t ah[4], al[4];
                    uint32_t o = (uint32_t)((warp_m * 64 + mf * 16) * PAD) * 2 + (uint32_t)(ks * 32) + aoff;
                    ldsm_x4(ah, tAh + o);
                    ldsm_x4(al, tAl + o);
                    #pragma unroll
                    for (int nf = 0; nf < 4; nf++) {
                        int n2 = nf >> 1, pb = (nf & 1) * 2;
                        float* cc = acc[mf][nf];
                        mma_bf(cc, ah, bh[n2][pb], bh[n2][pb + 1]);
                        mma_bf(cc, ah, bl[n2][pb], bl[n2][pb + 1]);
                        mma_bf(cc, al, bh[n2][pb], bh[n2][pb + 1]);
                    }
                }
            }
            __syncthreads();
        }

        #pragma unroll
        for (int mf = 0; mf < 4; mf++) {
            #pragma unroll
            for (int nf = 0; nf < 4; nf++) {
                int m0 = bm + warp_m * 64 + mf * 16 + rrow;
                int n0 = bn + warp_n * 32 + nf * 8 + rcol;
                float* cc = acc[mf][nf];
                #pragma unroll
                for (int half = 0; half < 2; half++) {
                    int mm = m0 + half * 8;
                    if (mm >= M) continue;
                    #pragma unroll
                    for (int jj = 0; jj < 2; jj++) {
                        int nn = n0 + jj;
                        if (nn >= N) continue;
                        float v = cc[half * 2 + jj];
                        if (full) C[(long)mm * ldc + nn] = v;
                        else atomicAdd(&C[(long)mm * ldc + nn], v);
                    }
                }
            }
        }
        __syncthreads();
        u0 = (long)tile * nch + c1;
    }
}

// =======================================================================
// Balanced AV GEMM: o[t, h*128+d] = sum_s P[h,t,s] * vt[h*128+d, s]
// chunks(m)=4(m+1); offset(h,m)=544h+2m(m+1); U=8704. 2-stage core.
// =======================================================================
__global__ void __launch_bounds__(256, 2)
av_split_k(const bf16* __restrict__ Ph, const bf16* __restrict__ Pl,
           const bf16* __restrict__ Vh, const bf16* __restrict__ Vl,
           float* __restrict__ C) {
    const long U = 8704;
    int G = gridDim.x;
    long u0 = (long)blockIdx.x * U / G;
    long u1 = ((long)blockIdx.x + 1) * U / G;

    extern __shared__ bf16 sm[];
    uint32_t smb = smem_to_u32(sm);
    int tid = threadIdx.x, lane = tid & 31, wid = tid >> 5;
    int warp_m = wid >> 2, warp_n = wid & 3;
    int srow0 = tid >> 2, sch = tid & 3;
    uint32_t aoff = ((uint32_t)((lane & 15) * PAD) + ((lane >> 4) << 3)) * 2;
    uint32_t boff = ((uint32_t)(((lane & 7) + ((lane >> 1) & 8)) * PAD) + (lane & 8)) * 2;
    int rrow = lane >> 2, rcol = (lane & 3) * 2;

    while (u0 < u1) {
        int h = (int)(u0 / 544);
        int rem = (int)(u0 - (long)h * 544);
        int m = 0;
        while (rem >= 2 * (m + 1) * (m + 2)) m++;
        int c0 = rem - 2 * m * (m + 1);
        int nchT = 4 * (m + 1);
        long avail = u1 - u0;
        int c1 = (c0 + avail < (long)nchT) ? (int)(c0 + avail) : nchT;
        bool full = (c0 == 0) && (c1 == nchT);
        int bm = m * 128;

        const bf16* Ah = Ph + (size_t)h * T * T;
        const bf16* Al = Pl + (size_t)h * T * T;
        const bf16* Bh = Vh + (size_t)h * 128 * T;
        const bf16* Bl = Vl + (size_t)h * 128 * T;

        float acc[4][4][4];
        #pragma unroll
        for (int i = 0; i < 4; i++)
            #pragma unroll
            for (int j = 0; j < 4; j++)
                #pragma unroll
                for (int q = 0; q < 4; q++) acc[i][j][q] = 0.f;

        auto load_chunk = [&](int c, int buf) {
            int k0 = c * BK;
            uint32_t base = smb + (uint32_t)buf * 4 * TILE_ELEMS * 2;
            #pragma unroll
            for (int it = 0; it < 2; it++) {
                int row = srow0 + it * 64;
                uint32_t soff = (uint32_t)(row * PAD + sch * 8) * 2;
                long ga = (long)(bm + row) * T + k0 + sch * 8;
                long gb = (long)row * T + k0 + sch * 8;
                cp16(base + 0 * TILE_ELEMS * 2 + soff, Ah + ga, true);
                cp16(base + 1 * TILE_ELEMS * 2 + soff, Al + ga, true);
                cp16(base + 2 * TILE_ELEMS * 2 + soff, Bh + gb, true);
                cp16(base + 3 * TILE_ELEMS * 2 + soff, Bl + gb, true);
            }
        };

        load_chunk(c0, 0);
        CP_COMMIT();

        for (int c = c0; c < c1; c++) {
            CP_WAIT0();
            __syncthreads();
            if (c + 1 < c1) { load_chunk(c + 1, (c - c0 + 1) & 1); CP_COMMIT(); }

            uint32_t base = smb + (uint32_t)((c - c0) & 1) * 4 * TILE_ELEMS * 2;
            uint32_t tAh = base, tAl = base + TILE_ELEMS * 2;
            uint32_t tBh = base + 2 * TILE_ELEMS * 2, tBl = base + 3 * TILE_ELEMS * 2;

            #pragma unroll
            for (int ks = 0; ks < 2; ks++) {
                uint32_t bh[2][4], bl[2][4];
                #pragma unroll
                for (int nf2 = 0; nf2 < 2; nf2++) {
                    uint32_t o = (uint32_t)((warp_n * 32 + nf2 * 16) * PAD) * 2 + (uint32_t)(ks * 32) + boff;
                    ldsm_x4(bh[nf2], tBh + o);
                    ldsm_x4(bl[nf2], tBl + o);
                }
                #pragma unroll
                for (int mf = 0; mf < 4; mf++) {
                    uint32_t ah[4], al[4];
                    uint32_t o = (uint32_t)((warp_m * 64 + mf * 16) * PAD) * 2 + (uint32_t)(ks * 32) + aoff;
                    ldsm_x4(ah, tAh + o);
                    ldsm_x4(al, tAl + o);
                    #pragma unroll
                    for (int nf = 0; nf < 4; nf++) {
                        int n2 = nf >> 1, pb = (nf & 1) * 2;
                        float* cc = acc[mf][nf];
                        mma_bf(cc, ah, bh[n2][pb], bh[n2][pb + 1]);
                        mma_bf(cc, ah, bl[n2][pb], bl[n2][pb + 1]);
                        mma_bf(cc, al, bh[n2][pb], bh[n2][pb + 1]);
                    }
                }
            }
            __syncthreads();
        }

        #pragma unroll
        for (int mf = 0; mf < 4; mf++) {
            #pragma unroll
            for (int nf = 0; nf < 4; nf++) {
                int m0 = bm + warp_m * 64 + mf * 16 + rrow;
                int n0 = h * 128 + warp_n * 32 + nf * 8 + rcol;
                float* cc = acc[mf][nf];
                #pragma unroll
                for (int half = 0; half < 2; half++) {
                    int mm = m0 + half * 8;
                    #pragma unroll
                    for (int jj = 0; jj < 2; jj++) {
                        int nn = n0 + jj;
                        float v = cc[half * 2 + jj];
                        if (full) C[(long)mm * HDV + nn] = v;
                        else atomicAdd(&C[(long)mm * HDV + nn], v);
                    }
                }
            }
        }
        __syncthreads();
        u0 += c1 - c0;
    }
}

// ---------------- weight transpose + bf16 split ----------------
__global__ void wtrans_k(const float* __restrict__ W, bf16* __restrict__ Oh,
                         bf16* __restrict__ Ol, int K, int N, long zso) {
    long z = blockIdx.z;
    W += z * (long)K * N;
    Oh += z * zso;
    Ol += z * zso;
    __shared__ float tile[32][33];
    int n0 = blockIdx.x * 32, k0 = blockIdx.y * 32;
    int tx = threadIdx.x, ty = threadIdx.y;
    #pragma unroll
    for (int i = 0; i < 4; i++)
        tile[ty + i * 8][tx] = W[(long)(k0 + ty + i * 8) * N + n0 + tx];
    __syncthreads();
    #pragma unroll
    for (int i = 0; i < 4; i++) {
        int n = n0 + ty + i * 8, k = k0 + tx;
        wr_hl(Oh, Ol, (size_t)n * K + k, tile[tx][ty + i * 8]);
    }
}

// ---------------- elementwise / norm ----------------
__global__ void rms_hl_k(const float* __restrict__ x, const float* __restrict__ w,
                         bf16* __restrict__ oh, bf16* __restrict__ ol,
                         int cols, int ldx, int ldo) {
    long row = blockIdx.x;
    const float* xr = x + row * ldx;
    float s = 0.f;
    for (int i = threadIdx.x; i < cols; i += blockDim.x) { float v = xr[i]; s += v * v; }
    s = blockReduceSum(s);
    float sc = rsqrtf(s / cols + 1e-6f);
    for (int i = threadIdx.x; i < cols; i += blockDim.x)
        wr_hl(oh, ol, row * ldo + i, xr[i] * sc * w[i]);
}

__global__ void addnorm_hl_k(const float* __restrict__ a, const float* __restrict__ b,
                             const float* __restrict__ w, float* __restrict__ res,
                             bf16* __restrict__ oh, bf16* __restrict__ ol) {
    long row = blockIdx.x;
    const float* ar = a + row * D;
    const float* br = b + row * D;
    float* rr = res + row * D;
    float s = 0.f;
    for (int i = threadIdx.x; i < D; i += blockDim.x) {
        float v = ar[i] + br[i];
        rr[i] = v;
        s += v * v;
    }
    s = blockReduceSum(s);
    float sc = rsqrtf(s / D + 1e-6f);
    for (int i = threadIdx.x; i < D; i += blockDim.x)
        wr_hl(oh, ol, row * D + i, rr[i] * sc * w[i]);
}

__global__ void cvt_hl_k(const float* __restrict__ x, bf16* __restrict__ oh,
                         bf16* __restrict__ ol, long n) {
    long i = (long)blockIdx.x * blockDim.x + threadIdx.x;
    if (i < n) wr_hl(oh, ol, i, x[i]);
}

__global__ void rope_cvt_q_k(const float* __restrict__ q, const int* __restrict__ pos) {
    int t = blockIdx.x;
    float fp = (float)pos[t];
    for (int e = threadIdx.x; e < QTOT; e += blockDim.x) {
        int h = e / QD, d = e % QD;
        const float* qr = q + (size_t)t * QTOT + h * QD;
        float v;
        if (d < DN) {
            v = qr[d];
        } else {
            int j = d - DN;
            int i = j & 31;
            float inv = 1.f / powf(10000.f, (float)i * (2.f / 64.f));
            float sn, cs;
            sincosf(fp * inv, &sn, &cs);
            float x1 = qr[DN + i], x2 = qr[DN + i + 32];
            v = (j < 32) ? (x1 * cs - x2 * sn) : (x2 * cs + x1 * sn);
        }
        wr_hl(qq_h, qq_l, (size_t)t * QTOT + e, v);
    }
}

__global__ void build_kh_k(const int* __restrict__ pos) {
    int t = blockIdx.x;
    __shared__ float kr[64];
    int tid = threadIdx.x;
    if (tid < 32) {
        int i = tid;
        float inv = 1.f / powf(10000.f, (float)i * (2.f / 64.f));
        float sn, cs;
        sincosf((float)pos[t] * inv, &sn, &cs);
        const float* kb = g_qkv + (size_t)t * NQKV + QL + KL;
        float x1 = kb[i], x2 = kb[i + 32];
        kr[i] = x1 * cs - x2 * sn;
        kr[i + 32] = x2 * cs + x1 * sn;
    }
    __syncthreads();
    for (int e = tid; e < QTOT; e += blockDim.x) {
        int h = e / QD, d = e % QD;
        float v = (d < DN) ? g_kvb[(size_t)t * KVBD + h * (DN + DV) + d] : kr[d - DN];
        wr_hl(kh_h, kh_l, (size_t)t * QTOT + e, v);
    }
}

__global__ void build_vt_k() {
    int t = blockIdx.x;
    const float* row = g_kvb + (size_t)t * KVBD;
    for (int e = threadIdx.x; e < H * DV; e += blockDim.x) {
        int h = e >> 7, d = e & 127;
        wr_hl(vt_h, vt_l, (size_t)e * T + t, row[h * (DN + DV) + DN + d]);
    }
}

__global__ void softmaxP_k() {
    int t = blockIdx.x, h = blockIdx.y;
    const float* row = g_scores + ((size_t)h * T + t) * (size_t)T;
    size_t po = ((size_t)h * T + t) * (size_t)T;
    int n = t + 1;
    const float alpha = 0.07216878364870322f;  // 1/sqrt(192)
    float m = -1e30f;
    for (int i = threadIdx.x; i < n; i += blockDim.x) m = fmaxf(m, row[i] * alpha);
    m = blockReduceMax(m);
    float s = 0.f;
    for (int i = threadIdx.x; i < n; i += blockDim.x) s += expf(row[i] * alpha - m);
    s = blockReduceSum(s);
    float inv = 1.f / s;
    for (int i = threadIdx.x; i < n; i += blockDim.x)
        wr_hl(P_h, P_l, po + i, expf(row[i] * alpha - m) * inv);
    // zero-fill only to end of this row's 128-tile (AV reads no further)
    int fend = ((t >> 7) + 1) << 7;
    bf16 zz = __float2bfloat16(0.f);
    for (int i = n + threadIdx.x; i < fend; i += blockDim.x) { P_h[po + i] = zz; P_l[po + i] = zz; }
}

__global__ void silumul_mlp_k() {
    long idx = (long)blockIdx.x * blockDim.x + threadIdx.x;
    if (idx >= (long)T * FF) return;
    long r = idx / FF;
    int c = (int)(idx % FF);
    float g = g_gu[r * (2 * FF) + c], u = g_gu[r * (2 * FF) + FF + c];
    wr_hl(ff_h, ff_l, idx, g / (1.f + expf(-g)) * u);
}

__global__ void silumul2_k() {
    long idx = (long)blockIdx.x * blockDim.x + threadIdx.x;
    if (idx >= (long)2 * T * EF) return;
    long r = idx / EF;
    int c = (int)(idx % EF);
    float g = g_mgu[r * (2 * EF) + c], u = g_mgu[r * (2 * EF) + EF + c];
    wr_hl(mh_h, mh_l, idx, g / (1.f + expf(-g)) * u);
}

// ---------------- MoE routing ----------------
__global__ void top2_k() {
    int t = blockIdx.x * blockDim.x + threadIdx.x;
    if (t >= T) return;
    const float* l = g_logits + (size_t)t * E;
    int i0 = 0;
    float v0 = l[0];
    for (int i = 1; i < E; i++)
        if (l[i] > v0) { v0 = l[i]; i0 = i; }
    int i1 = -1;
    float v1 = -1e30f;
    for (int i = 0; i < E; i++)
        if (i != i0 && l[i] > v1) { v1 = l[i]; i1 = i; }
    float e = expf(v1 - v0);
    g_expid[2 * t] = i0;
    g_expid[2 * t + 1] = i1;
    g_gate[2 * t] = 1.f / (1.f + e);
    g_gate[2 * t + 1] = e / (1.f + e);
}
__global__ void zero_cnt_k() { if (threadIdx.x < E) g_cnt[threadIdx.x] = 0; }
__global__ void count_k() {
    int p = blockIdx.x * blockDim.x + threadIdx.x;
    if (p < 2 * T) g_slot[p] = atomicAdd(&g_cnt[g_expid[p]], 1);
}
__global__ void scan_k() {
    if (threadIdx.x == 0) {
        int o = 0;
        for (int e = 0; e < E; e++) { g_off[e] = o; o += g_cnt[e]; }
    }
}
__global__ void gather_k() {
    int p = blockIdx.x;
    int row = g_off[g_expid[p]] + g_slot[p];
    if (threadIdx.x == 0) g_rowOf[p] = row;
    size_t src = (size_t)(p >> 1) * D, dst = (size_t)row * D;
    for (int i = threadIdx.x; i < D; i += blockDim.x) {
        mx_h[dst + i] = x_h[src + i];
        mx_l[dst + i] = x_l[src + i];
    }
}
__global__ void moecomb_k() {
    long idx = (long)blockIdx.x * blockDim.x + threadIdx.x;
    if (idx >= (long)T * D) return;
    long t = idx / D;
    int d = (int)(idx % D);
    g_moe[idx] = g_gate[2 * t] * g_my[(size_t)g_rowOf[2 * t] * D + d] +
                 g_gate[2 * t + 1] * g_my[(size_t)g_rowOf[2 * t + 1] * D + d];
}
__global__ void add_k(const float* __restrict__ a, const float* __restrict__ b,
                      float* __restrict__ o, long n) {
    long idx = (long)blockIdx.x * blockDim.x + threadIdx.x;
    if (idx < n) o[idx] = a[idx] + b[idx];
}

// ---------------- host side ----------------
static void bgemm_f(const bf16* Ah, const bf16* Al, const bf16* Bh, const bf16* Bl,
                    float* C, int M, int N, int K, int lda, int ldb, int ldc,
                    long sA, long sB, long sC, int batch, int cskip) {
    dim3 g((N + BN - 1) / BN, (M + BM - 1) / BM, batch);
    bgemm_k<false><<<g, 256, GSMEM>>>(Ah, Al, Bh, Bl, C, M, N, K, lda, ldb, ldc,
                                      sA, sB, sC, cskip, nullptr, nullptr);
}
static void bgemm_seg(const bf16* Ah, const bf16* Al, const bf16* Bh, const bf16* Bl,
                      float* C, int N, int K, int lda, int ldb, int ldc, long sB,
                      const int* off, const int* cnt) {
    dim3 g((N + BN - 1) / BN, (2 * T + BM - 1) / BM, E);
    bgemm_k<true><<<g, 256, GSMEM>>>(Ah, Al, Bh, Bl, C, 0, N, K, lda, ldb, ldc,
                                     0, sB, 0, 0, off, cnt);
}
static void sgemm_split(const bf16* Ah, const bf16* Al, const bf16* Bh, const bf16* Bl,
                        float* C, int M, int N, int K, int lda, int ldb, int ldc) {
    cudaMemsetAsync(C, 0, (size_t)M * ldc * sizeof(float));
    int mt = (M + BM - 1) / BM, nt = (N + BN - 1) / BN;
    long U = (long)mt * nt * (K / BK);
    int G = U < GPERS ? (int)U : GPERS;
    sgemm_split_k<<<G, 256, GSMEM>>>(Ah, Al, Bh, Bl, C, M, N, K, lda, ldb, ldc, mt, nt);
}

extern "C" void kernel_launch(void* const* d_in, const int* in_sizes, int n_in,
                              void* d_out, int out_size) {
    const float* hidden = (const float*)d_in[0];
    const int* pos = (const int*)d_in[1];
    const float* ln_in = (const float*)d_in[2];
    const float* ln_post = (const float*)d_in[3];
    const float* wqa = (const float*)d_in[4];
    const float* qnorm = (const float*)d_in[5];
    const float* wqb = (const float*)d_in[6];
    const float* wkva = (const float*)d_in[7];
    const float* kvnorm = (const float*)d_in[8];
    const float* wkvb = (const float*)d_in[9];
    const float* wo = (const float*)d_in[10];
    const float* wgu = (const float*)d_in[11];
    const float* wd = (const float*)d_in[12];
    const float* rw = (const float*)d_in[13];
    const float* mwg = (const float*)d_in[14];
    const float* mwu = (const float*)d_in[15];
    const float* mwd = (const float*)d_in[16];
    float* out = (float*)d_out;

    cudaFuncSetAttribute(bgemm_k<false>, cudaFuncAttributeMaxDynamicSharedMemorySize, GSMEM);
    cudaFuncSetAttribute(bgemm_k<true>, cudaFuncAttributeMaxDynamicSharedMemorySize, GSMEM);
    cudaFuncSetAttribute(sgemm_split_k, cudaFuncAttributeMaxDynamicSharedMemorySize, GSMEM);
    cudaFuncSetAttribute(av_split_k, cudaFuncAttributeMaxDynamicSharedMemorySize, GSMEM);

    void* p;
#define SYMF(name) cudaGetSymbolAddress(&p, name); float* p_##name = (float*)p;
#define SYMB(name) cudaGetSymbolAddress(&p, name); bf16* p_##name = (bf16*)p;
#define SYMI(name) cudaGetSymbolAddress(&p, name); int* p_##name = (int*)p;
    SYMF(g_res) SYMF(g_h) SYMF(g_moe) SYMF(g_qkv) SYMF(g_q) SYMF(g_kvb) SYMF(g_attno)
    SYMF(g_scores) SYMF(g_gu) SYMF(g_mgu) SYMF(g_my) SYMF(g_logits)
    SYMB(x_h) SYMB(x_l) SYMB(qln_h) SYMB(qln_l) SYMB(qq_h) SYMB(qq_l)
    SYMB(kvcn_h) SYMB(kvcn_l) SYMB(kh_h) SYMB(kh_l) SYMB(vt_h) SYMB(vt_l)
    SYMB(P_h) SYMB(P_l) SYMB(ao_h) SYMB(ao_l) SYMB(ff_h) SYMB(ff_l)
    SYMB(mx_h) SYMB(mx_l) SYMB(mh_h) SYMB(mh_l)
    SYMB(wqkvT_h) SYMB(wqkvT_l) SYMB(wqbT_h) SYMB(wqbT_l)
    SYMB(wkvbT_h) SYMB(wkvbT_l) SYMB(woT_h) SYMB(woT_l) SYMB(wguT_h) SYMB(wguT_l)
    SYMB(wdT_h) SYMB(wdT_l) SYMB(rwT_h) SYMB(rwT_l)
    SYMB(mwguT_h) SYMB(mwguT_l) SYMB(mwdT_h) SYMB(mwdT_l)
    SYMI(g_cnt) SYMI(g_off)
#undef SYMF
#undef SYMB
#undef SYMI

    dim3 tb(32, 8);
    long zqkv = (long)NQKV * D;

    // kernels: rms(0), wtrans(1), wtrans(2), sgemm_split(3) <- ncu target
    rms_hl_k<<<T, 256>>>(hidden, ln_in, p_x_h, p_x_l, D, D, D);
    wtrans_k<<<dim3(QL / 32, D / 32, 2), tb>>>(wqa, p_wqkvT_h, p_wqkvT_l, D, QL, zqkv);
    wtrans_k<<<dim3(KVD / 32, D / 32, 2), tb>>>(wkva, p_wqkvT_h + (size_t)QL * D,
                                                p_wqkvT_l + (size_t)QL * D, D, KVD, zqkv);
    sgemm_split(p_x_h, p_x_l, p_wqkvT_h, p_wqkvT_l, p_g_qkv, T, NQKV, D, D, D, NQKV);
    // remaining weight preps
    wtrans_k<<<dim3(QTOT / 32, QL / 32, 2), tb>>>(wqb, p_wqbT_h, p_wqbT_l, QL, QTOT,
                                                  (long)QTOT * QL);
    wtrans_k<<<dim3(KVBD / 32, KL / 32, 2), tb>>>(wkvb, p_wkvbT_h, p_wkvbT_l, KL, KVBD,
                                                  (long)KVBD * KL);
    wtrans_k<<<dim3(D / 32, D / 32, 2), tb>>>(wo, p_woT_h, p_woT_l, HDV, D, (long)D * D);
    wtrans_k<<<dim3(2 * FF / 32, D / 32, 2), tb>>>(wgu, p_wguT_h, p_wguT_l, D, 2 * FF,
                                                   (long)2 * FF * D);
    wtrans_k<<<dim3(D / 32, FF / 32, 2), tb>>>(wd, p_wdT_h, p_wdT_l, FF, D, (long)D * FF);
    wtrans_k<<<dim3(E / 32, D / 32, 1), tb>>>(rw, p_rwT_h, p_rwT_l, D, E, 0);
    wtrans_k<<<dim3(EF / 32, D / 32, E), tb>>>(mwg, p_mwguT_h, p_mwguT_l, D, EF,
                                               (long)2 * EF * D);
    wtrans_k<<<dim3(EF / 32, D / 32, E), tb>>>(mwu, p_mwguT_h + (size_t)EF * D,
                                               p_mwguT_l + (size_t)EF * D, D, EF,
                                               (long)2 * EF * D);
    wtrans_k<<<dim3(D / 32, EF / 32, E), tb>>>(mwd, p_mwdT_h, p_mwdT_l, EF, D, (long)D * EF);

    auto mla = [&](int l, float* outbuf, bool qkv_done) {
        if (!qkv_done)
            sgemm_split(p_x_h, p_x_l, p_wqkvT_h + (size_t)l * zqkv, p_wqkvT_l + (size_t)l * zqkv,
                        p_g_qkv, T, NQKV, D, D, D, NQKV);
        rms_hl_k<<<T, 256>>>(p_g_qkv, qnorm + (size_t)l * QL, p_qln_h, p_qln_l, QL, NQKV, QL);
        sgemm_split(p_qln_h, p_qln_l, p_wqbT_h + (size_t)l * QTOT * QL,
                    p_wqbT_l + (size_t)l * QTOT * QL, p_g_q, T, QTOT, QL, QL, QL, QTOT);
        rms_hl_k<<<T, 256>>>(p_g_qkv + QL, kvnorm + (size_t)l * KL, p_kvcn_h, p_kvcn_l,
                             KL, NQKV, KL);
        sgemm_split(p_kvcn_h, p_kvcn_l, p_wkvbT_h + (size_t)l * KVBD * KL,
                    p_wkvbT_l + (size_t)l * KVBD * KL, p_g_kvb, T, KVBD, KL, KL, KL, KVBD);
        rope_cvt_q_k<<<T, 256>>>(p_g_q, pos);
        build_kh_k<<<T, 256>>>(pos);
        build_vt_k<<<T, 256>>>();
        bgemm_f(p_qq_h, p_qq_l, p_kh_h, p_kh_l, p_g_scores, T, T, QD,
                QTOT, QTOT, T, QD, QD, (long)T * T, H, 1);
        softmaxP_k<<<dim3(T, H), 256>>>();
        cudaMemsetAsync(p_g_attno, 0, (size_t)T * HDV * sizeof(float));
        av_split_k<<<GPERS, 256, GSMEM>>>(p_P_h, p_P_l, p_vt_h, p_vt_l, p_g_attno);
        cvt_hl_k<<<(int)(((long)T * HDV + 255) / 256), 256>>>(p_g_attno, p_ao_h, p_ao_l,
                                                              (long)T * HDV);
        sgemm_split(p_ao_h, p_ao_l, p_woT_h + (size_t)l * D * D, p_woT_l + (size_t)l * D * D,
                    outbuf, T, D, HDV, HDV, HDV, D);
    };

    auto mlp = [&](int l, float* outbuf) {
        sgemm_split(p_x_h, p_x_l, p_wguT_h + (size_t)l * 2 * FF * D,
                    p_wguT_l + (size_t)l * 2 * FF * D, p_g_gu, T, 2 * FF, D, D, D, 2 * FF);
        silumul_mlp_k<<<(int)(((long)T * FF + 255) / 256), 256>>>();
        sgemm_split(p_ff_h, p_ff_l, p_wdT_h + (size_t)l * D * FF, p_wdT_l + (size_t)l * D * FF,
                    outbuf, T, D, FF, FF, FF, D);
    };

    // ================= forward =================
    mla(0, p_g_h, true);
    addnorm_hl_k<<<T, 256>>>(p_g_h, hidden, ln_post, p_g_res, p_x_h, p_x_l);

    // ---- MoE ----
    sgemm_split(p_x_h, p_x_l, p_rwT_h, p_rwT_l, p_g_logits, T, E, D, D, D, E);
    top2_k<<<(T + 255) / 256, 256>>>();
    zero_cnt_k<<<1, 32>>>();
    count_k<<<(2 * T + 255) / 256, 256>>>();
    scan_k<<<1, 32>>>();
    gather_k<<<2 * T, 256>>>();
    bgemm_seg(p_mx_h, p_mx_l, p_mwguT_h, p_mwguT_l, p_g_mgu, 2 * EF, D, D, D, 2 * EF,
              (long)2 * EF * D, p_g_off, p_g_cnt);
    silumul2_k<<<(int)(((long)2 * T * EF + 255) / 256), 256>>>();
    bgemm_seg(p_mh_h, p_mh_l, p_mwdT_h, p_mwdT_l, p_g_my, D, EF, EF, EF, D,
              (long)D * EF, p_g_off, p_g_cnt);
    moecomb_k<<<(int)(((long)T * D + 255) / 256), 256>>>();

    // ---- MLP layer 0 ----
    mlp(0, p_g_h);
    addnorm_hl_k<<<T, 256>>>(p_g_h, p_g_res, ln_in + D, p_g_res, p_x_h, p_x_l);

    // ---- layer 1 ----
    mla(1, p_g_h, false);
    addnorm_hl_k<<<T, 256>>>(p_g_h, p_g_res, ln_post + D, p_g_res, p_x_h, p_x_l);
    mlp(1, p_g_h);

    add_k<<<(int)(((long)T * D + 255) / 256), 256>>>(p_g_h, p_g_moe, out, (long)T * D);
}